// round 1
// baseline (speedup 1.0000x reference)
#include <cuda_runtime.h>
#include <cuda_bf16.h>
#include <math.h>

// Problem constants
#define SEQ     4096
#define DIM     1024
#define NHEADS  16
#define NKV     4
#define HD      64     // head dim
#define KVDIM   256    // NKV * HD

// ---------------------------------------------------------------------------
// Scratch (no cudaMalloc allowed — device globals)
// ---------------------------------------------------------------------------
__device__ float g_q[SEQ * DIM];      // 16 MB
__device__ float g_k[SEQ * KVDIM];    // 4 MB
__device__ float g_v[SEQ * KVDIM];    // 4 MB
__device__ float g_attn[SEQ * DIM];   // 16 MB

// ---------------------------------------------------------------------------
// GEMM: C[M,N] = A[M,K] @ B[N,K]^T   (both row-major, "NT" form)
// BM=BN=64, BK=16, 256 threads, 4x4 microtile per thread.
// Smem tiles stored K-major (transposed) so inner loop uses float4 LDS.
// ---------------------------------------------------------------------------
#define GBM 64
#define GBN 64
#define GBK 16
#define GPAD 68   // pad (multiple of 4 for aligned float4) to cut bank conflicts

__global__ __launch_bounds__(256) void gemm_nt(const float* __restrict__ A,
                                               const float* __restrict__ B,
                                               float* __restrict__ C,
                                               int M, int N, int K) {
    __shared__ float As[GBK][GPAD];   // [k][m]
    __shared__ float Bs[GBK][GPAD];   // [k][n]

    const int tid = threadIdx.x;
    const int tx = tid & 15;
    const int ty = tid >> 4;
    const int row0 = blockIdx.y * GBM;
    const int col0 = blockIdx.x * GBN;

    float acc[4][4] = {};

    for (int k0 = 0; k0 < K; k0 += GBK) {
        // Load tiles: 64 rows x 16 k = 256 float4 per tile, one per thread.
        {
            int r  = tid >> 2;            // 0..63
            int kq = (tid & 3) << 2;      // 0,4,8,12
            float4 a = *(const float4*)&A[(size_t)(row0 + r) * K + k0 + kq];
            As[kq + 0][r] = a.x; As[kq + 1][r] = a.y;
            As[kq + 2][r] = a.z; As[kq + 3][r] = a.w;
            float4 b = *(const float4*)&B[(size_t)(col0 + r) * K + k0 + kq];
            Bs[kq + 0][r] = b.x; Bs[kq + 1][r] = b.y;
            Bs[kq + 2][r] = b.z; Bs[kq + 3][r] = b.w;
        }
        __syncthreads();

#pragma unroll
        for (int kk = 0; kk < GBK; kk++) {
            float4 a = *(const float4*)&As[kk][ty << 2];
            float4 b = *(const float4*)&Bs[kk][tx << 2];
            float av[4] = {a.x, a.y, a.z, a.w};
            float bv[4] = {b.x, b.y, b.z, b.w};
#pragma unroll
            for (int i = 0; i < 4; i++)
#pragma unroll
                for (int j = 0; j < 4; j++)
                    acc[i][j] += av[i] * bv[j];
        }
        __syncthreads();
    }

#pragma unroll
    for (int i = 0; i < 4; i++) {
        float* crow = &C[(size_t)(row0 + (ty << 2) + i) * N + col0 + (tx << 2)];
        float4 o = make_float4(acc[i][0], acc[i][1], acc[i][2], acc[i][3]);
        *(float4*)crow = o;
    }
}

// ---------------------------------------------------------------------------
// RoPE (in place): buf is [SEQ, ncols], ncols = heads*64. Pair (2i,2i+1) within
// each 64-dim head rotated by (cos[s,i], sin[s,i]), i in [0,32).
// ---------------------------------------------------------------------------
__global__ void rope_kernel(float* __restrict__ buf,
                            const float* __restrict__ cosb,
                            const float* __restrict__ sinb,
                            int ncols, int total_pairs) {
    int idx = blockIdx.x * blockDim.x + threadIdx.x;
    if (idx >= total_pairs) return;
    int ppr = ncols >> 1;           // pairs per row
    int s = idx / ppr;
    int p = idx - s * ppr;
    int i = p & 31;                 // pair index within head
    int col = ((p >> 5) << 6) + (i << 1);
    float c  = cosb[s * 32 + i];
    float sn = sinb[s * 32 + i];
    float* base = &buf[(size_t)s * ncols + col];
    float xr = base[0], xi = base[1];
    base[0] = xr * c - xi * sn;
    base[1] = xr * sn + xi * c;
}

// ---------------------------------------------------------------------------
// Flash attention, fp32, causal, GQA (head h reads kv head h/4).
// Tile: 64 queries x 64 keys x 64 dims. 256 threads, 4x4 microtiles.
// Smem: Qt (persistent, K-major), KP (K tile K-major, then aliased as P tile
// c-major), Vs (row-major). All padded to 68 floats per row.
// ---------------------------------------------------------------------------
#define FPAD 68
#define FLASH_SMEM (3 * 64 * FPAD * 4)

extern __shared__ float fsm[];

__global__ __launch_bounds__(256) void flash_kernel(const float* __restrict__ Q,
                                                    const float* __restrict__ K,
                                                    const float* __restrict__ V,
                                                    float* __restrict__ O) {
    const int qt = blockIdx.x;      // query tile (0..63)
    const int h  = blockIdx.y;      // head (0..15)
    const int kvh = h >> 2;
    const int tid = threadIdx.x;
    const int tx = tid & 15;
    const int ty = tid >> 4;
    const int q0 = qt * 64;

    float* Qt = fsm;                 // [64 d][68]
    float* KP = fsm + 64 * FPAD;     // K: [64 d][68]  /  P: [64 c][68]
    float* Vs = fsm + 2 * 64 * FPAD; // [64 c][68]

    // Load Q tile (scaled by 1/sqrt(64)=0.125), stored K-major.
#pragma unroll
    for (int it = 0; it < 4; it++) {
        int lin = tid + 256 * it;           // 0..1023 float4 slots
        int r  = lin >> 4;                  // query row 0..63
        int d4 = (lin & 15) << 2;           // dim 0..60
        float4 v = *(const float4*)&Q[(size_t)(q0 + r) * DIM + h * HD + d4];
        Qt[(d4 + 0) * FPAD + r] = v.x * 0.125f;
        Qt[(d4 + 1) * FPAD + r] = v.y * 0.125f;
        Qt[(d4 + 2) * FPAD + r] = v.z * 0.125f;
        Qt[(d4 + 3) * FPAD + r] = v.w * 0.125f;
    }

    float m[4], l[4], oacc[4][4];
#pragma unroll
    for (int i = 0; i < 4; i++) {
        m[i] = -1e30f; l[i] = 0.f;
#pragma unroll
        for (int j = 0; j < 4; j++) oacc[i][j] = 0.f;
    }

    for (int kt = 0; kt <= qt; kt++) {
        const int k0 = kt * 64;
        __syncthreads();   // prev iter's P/V reads done before overwrite (also covers Q load, iter 0)

        // Load K (K-major into KP) and V (row-major into Vs).
#pragma unroll
        for (int it = 0; it < 4; it++) {
            int lin = tid + 256 * it;
            int r  = lin >> 4;
            int d4 = (lin & 15) << 2;
            float4 kv = *(const float4*)&K[(size_t)(k0 + r) * KVDIM + kvh * HD + d4];
            KP[(d4 + 0) * FPAD + r] = kv.x;
            KP[(d4 + 1) * FPAD + r] = kv.y;
            KP[(d4 + 2) * FPAD + r] = kv.z;
            KP[(d4 + 3) * FPAD + r] = kv.w;
            float4 vv = *(const float4*)&V[(size_t)(k0 + r) * KVDIM + kvh * HD + d4];
            *(float4*)&Vs[r * FPAD + d4] = vv;
        }
        __syncthreads();

        // S = Q K^T (scaled)
        float s[4][4] = {};
#pragma unroll
        for (int kk = 0; kk < 64; kk++) {
            float4 a = *(const float4*)&Qt[kk * FPAD + (ty << 2)];
            float4 b = *(const float4*)&KP[kk * FPAD + (tx << 2)];
            float av[4] = {a.x, a.y, a.z, a.w};
            float bv[4] = {b.x, b.y, b.z, b.w};
#pragma unroll
            for (int i = 0; i < 4; i++)
#pragma unroll
                for (int j = 0; j < 4; j++)
                    s[i][j] += av[i] * bv[j];
        }

        // Causal mask on the diagonal tile (q0 == k0).
        if (kt == qt) {
#pragma unroll
            for (int i = 0; i < 4; i++)
#pragma unroll
                for (int j = 0; j < 4; j++)
                    if (((tx << 2) + j) > ((ty << 2) + i)) s[i][j] = -1e30f;
        }

        // Online softmax update.
#pragma unroll
        for (int i = 0; i < 4; i++) {
            float mx = fmaxf(fmaxf(s[i][0], s[i][1]), fmaxf(s[i][2], s[i][3]));
#pragma unroll
            for (int off = 8; off >= 1; off >>= 1)
                mx = fmaxf(mx, __shfl_xor_sync(0xffffffffu, mx, off));
            float mn = fmaxf(m[i], mx);
            float alpha = __expf(m[i] - mn);
            float sum = 0.f;
#pragma unroll
            for (int j = 0; j < 4; j++) {
                float p = __expf(s[i][j] - mn);
                s[i][j] = p;
                sum += p;
            }
#pragma unroll
            for (int off = 8; off >= 1; off >>= 1)
                sum += __shfl_xor_sync(0xffffffffu, sum, off);
            l[i] = l[i] * alpha + sum;
            m[i] = mn;
#pragma unroll
            for (int j = 0; j < 4; j++) oacc[i][j] *= alpha;
        }

        __syncthreads();   // everyone done reading K before P overwrites KP

        // Store P (c-major: P[c][r]) into KP.
#pragma unroll
        for (int i = 0; i < 4; i++)
#pragma unroll
            for (int j = 0; j < 4; j++)
                KP[((tx << 2) + j) * FPAD + (ty << 2) + i] = s[i][j];
        __syncthreads();

        // O += P V
#pragma unroll
        for (int c = 0; c < 64; c++) {
            float4 p = *(const float4*)&KP[c * FPAD + (ty << 2)];
            float4 v = *(const float4*)&Vs[c * FPAD + (tx << 2)];
            float pv[4] = {p.x, p.y, p.z, p.w};
            float vv[4] = {v.x, v.y, v.z, v.w};
#pragma unroll
            for (int i = 0; i < 4; i++)
#pragma unroll
                for (int j = 0; j < 4; j++)
                    oacc[i][j] += pv[i] * vv[j];
        }
    }

    // Write normalized output: [s, h*64 + d]
#pragma unroll
    for (int i = 0; i < 4; i++) {
        float inv = 1.f / l[i];
        float* orow = &O[(size_t)(q0 + (ty << 2) + i) * DIM + h * HD + (tx << 2)];
        float4 o = make_float4(oacc[i][0] * inv, oacc[i][1] * inv,
                               oacc[i][2] * inv, oacc[i][3] * inv);
        *(float4*)orow = o;
    }
}

// ---------------------------------------------------------------------------
// Launch
// ---------------------------------------------------------------------------
extern "C" void kernel_launch(void* const* d_in, const int* in_sizes, int n_in,
                              void* d_out, int out_size) {
    const float* x  = (const float*)d_in[0];
    const float* fc = (const float*)d_in[1];
    const float* fs = (const float*)d_in[2];
    const float* wq = (const float*)d_in[3];
    const float* wk = (const float*)d_in[4];
    const float* wv = (const float*)d_in[5];
    const float* wo = (const float*)d_in[6];
    float* out = (float*)d_out;

    static float *pq = nullptr, *pk = nullptr, *pv = nullptr, *pa = nullptr;
    if (!pq) {
        cudaGetSymbolAddress((void**)&pq, g_q);
        cudaGetSymbolAddress((void**)&pk, g_k);
        cudaGetSymbolAddress((void**)&pv, g_v);
        cudaGetSymbolAddress((void**)&pa, g_attn);
        cudaFuncSetAttribute(flash_kernel,
                             cudaFuncAttributeMaxDynamicSharedMemorySize,
                             FLASH_SMEM);
    }

    dim3 blk(256);
    // Projections: q = x @ wq^T, k = x @ wk^T, v = x @ wv^T
    gemm_nt<<<dim3(DIM / GBN,   SEQ / GBM), blk>>>(x, wq, pq, SEQ, DIM,   DIM);
    gemm_nt<<<dim3(KVDIM / GBN, SEQ / GBM), blk>>>(x, wk, pk, SEQ, KVDIM, DIM);
    gemm_nt<<<dim3(KVDIM / GBN, SEQ / GBM), blk>>>(x, wv, pv, SEQ, KVDIM, DIM);

    // RoPE on q and k
    rope_kernel<<<(SEQ * (DIM / 2)   + 255) / 256, 256>>>(pq, fc, fs, DIM,   SEQ * (DIM / 2));
    rope_kernel<<<(SEQ * (KVDIM / 2) + 255) / 256, 256>>>(pk, fc, fs, KVDIM, SEQ * (KVDIM / 2));

    // Flash attention
    flash_kernel<<<dim3(SEQ / 64, NHEADS), blk, FLASH_SMEM>>>(pq, pk, pv, pa);

    // Output projection: out = attn @ wo^T
    gemm_nt<<<dim3(DIM / GBN, SEQ / GBM), blk>>>(pa, wo, out, SEQ, DIM, DIM);
}

// round 2
// speedup vs baseline: 2.8837x; 2.8837x over previous
#include <cuda_runtime.h>
#include <cuda_bf16.h>
#include <stdint.h>
#include <math.h>

// Problem constants
#define SEQ     4096
#define DIM     1024
#define NHEADS  16
#define NKV     4
#define HD      64
#define KVDIM   256

// ---------------------------------------------------------------------------
// Scratch (device globals; cudaMalloc is forbidden)
// ---------------------------------------------------------------------------
__device__ float g_q[SEQ * DIM];
__device__ float g_k[SEQ * KVDIM];
__device__ float g_v[SEQ * KVDIM];
__device__ float g_attn[SEQ * DIM];

// ---------------------------------------------------------------------------
// tf32 helpers
// ---------------------------------------------------------------------------
__device__ __forceinline__ uint32_t f2tf32(float x) {
    uint32_t r;
    asm("cvt.rna.tf32.f32 %0, %1;" : "=r"(r) : "f"(x));
    return r;
}

__device__ __forceinline__ void mma_tf32(float c[4], const uint32_t a[4],
                                         const uint32_t b[2]) {
    asm volatile(
        "mma.sync.aligned.m16n8k8.row.col.f32.tf32.tf32.f32 "
        "{%0,%1,%2,%3},{%4,%5,%6,%7},{%8,%9},{%0,%1,%2,%3};"
        : "+f"(c[0]), "+f"(c[1]), "+f"(c[2]), "+f"(c[3])
        : "r"(a[0]), "r"(a[1]), "r"(a[2]), "r"(a[3]),
          "r"(b[0]), "r"(b[1]));
}

// ---------------------------------------------------------------------------
// tf32 GEMM: C[M,N] = A[M,K] @ B[N,K]^T, row-major A and B.
// BM=128, BN=64, BK=32, 256 threads (8 warps, 4m x 2n), warp tile 32x32.
// ---------------------------------------------------------------------------
#define GBM 128
#define GBN 64
#define GBK 32
#define GPD 36   // smem row pitch (words): (36*g + c) % 32 = (4g+c)%32, conflict-free frags

__global__ __launch_bounds__(256) void gemm_tf32(const float* __restrict__ A,
                                                 const float* __restrict__ B,
                                                 float* __restrict__ C,
                                                 int M, int N, int K) {
    __shared__ uint32_t As[GBM][GPD];
    __shared__ uint32_t Bs[GBN][GPD];

    const int tid = threadIdx.x;
    const int wid = tid >> 5;
    const int lane = tid & 31;
    const int g = lane >> 2;   // group id (row within 8)
    const int c = lane & 3;    // thread-in-group (col within 4)
    const int wm = wid >> 1;   // 0..3
    const int wn = wid & 1;    // 0..1
    const int row0 = blockIdx.y * GBM;
    const int col0 = blockIdx.x * GBN;

    float acc[2][4][4] = {};

    for (int k0 = 0; k0 < K; k0 += GBK) {
        // A: 128x32 floats = 4 float4/thread. B: 64x32 = 2 float4/thread.
#pragma unroll
        for (int i = 0; i < 4; i++) {
            int lin = tid + 256 * i;
            int r  = lin >> 3;
            int kq = (lin & 7) << 2;
            float4 v = *(const float4*)&A[(size_t)(row0 + r) * K + k0 + kq];
            As[r][kq + 0] = f2tf32(v.x); As[r][kq + 1] = f2tf32(v.y);
            As[r][kq + 2] = f2tf32(v.z); As[r][kq + 3] = f2tf32(v.w);
        }
#pragma unroll
        for (int i = 0; i < 2; i++) {
            int lin = tid + 256 * i;
            int r  = lin >> 3;
            int kq = (lin & 7) << 2;
            float4 v = *(const float4*)&B[(size_t)(col0 + r) * K + k0 + kq];
            Bs[r][kq + 0] = f2tf32(v.x); Bs[r][kq + 1] = f2tf32(v.y);
            Bs[r][kq + 2] = f2tf32(v.z); Bs[r][kq + 3] = f2tf32(v.w);
        }
        __syncthreads();

#pragma unroll
        for (int kk = 0; kk < 4; kk++) {
            uint32_t a[2][4];
#pragma unroll
            for (int mt = 0; mt < 2; mt++) {
                int mb = wm * 32 + mt * 16;
                a[mt][0] = As[mb + g][kk * 8 + c];
                a[mt][1] = As[mb + g + 8][kk * 8 + c];
                a[mt][2] = As[mb + g][kk * 8 + c + 4];
                a[mt][3] = As[mb + g + 8][kk * 8 + c + 4];
            }
#pragma unroll
            for (int nt = 0; nt < 4; nt++) {
                uint32_t b[2];
                int nb = wn * 32 + nt * 8;
                b[0] = Bs[nb + g][kk * 8 + c];
                b[1] = Bs[nb + g][kk * 8 + c + 4];
#pragma unroll
                for (int mt = 0; mt < 2; mt++)
                    mma_tf32(acc[mt][nt], a[mt], b);
            }
        }
        __syncthreads();
    }

#pragma unroll
    for (int mt = 0; mt < 2; mt++) {
#pragma unroll
        for (int nt = 0; nt < 4; nt++) {
            int r = row0 + wm * 32 + mt * 16 + g;
            int col = col0 + wn * 32 + nt * 8 + 2 * c;
            *(float2*)&C[(size_t)r * N + col] =
                make_float2(acc[mt][nt][0], acc[mt][nt][1]);
            *(float2*)&C[(size_t)(r + 8) * N + col] =
                make_float2(acc[mt][nt][2], acc[mt][nt][3]);
        }
    }
}

// ---------------------------------------------------------------------------
// RoPE (in place), unchanged from baseline.
// ---------------------------------------------------------------------------
__global__ void rope_kernel(float* __restrict__ buf,
                            const float* __restrict__ cosb,
                            const float* __restrict__ sinb,
                            int ncols, int total_pairs) {
    int idx = blockIdx.x * blockDim.x + threadIdx.x;
    if (idx >= total_pairs) return;
    int ppr = ncols >> 1;
    int s = idx / ppr;
    int p = idx - s * ppr;
    int i = p & 31;
    int col = ((p >> 5) << 6) + (i << 1);
    float cth = cosb[s * 32 + i];
    float sth = sinb[s * 32 + i];
    float* base = &buf[(size_t)s * ncols + col];
    float xr = base[0], xi = base[1];
    base[0] = xr * cth - xi * sth;
    base[1] = xr * sth + xi * cth;
}

// ---------------------------------------------------------------------------
// Flash attention, tf32 mma, causal, GQA.
// Block: 128 threads (4 warps), q-tile 64, k-tile 64. Warp w owns q rows
// [16w, 16w+16) x all 64 keys: 8 n-tiles x 8 k-steps of m16n8k8.
// P is re-fragmented through smem (per-warp private region).
// ---------------------------------------------------------------------------
#define QPD 68   // (4g+c)%32 unique -> conflict-free A/B frag loads
#define VPD 72   // (8c+g)%32 unique -> conflict-free V B-frag loads

// smem words: Qs 64*68, Ks 64*68, Vs 64*72, Ps 64*68
#define FL_QS   0
#define FL_KS   (64 * QPD)
#define FL_VS   (FL_KS + 64 * QPD)
#define FL_PS   (FL_VS + 64 * VPD)
#define FL_WORDS (FL_PS + 64 * QPD)
#define FLASH_SMEM (FL_WORDS * 4)

extern __shared__ uint32_t fsm[];

__global__ __launch_bounds__(128) void flash_tf32(const float* __restrict__ Q,
                                                  const float* __restrict__ K,
                                                  const float* __restrict__ V,
                                                  float* __restrict__ O) {
    const int qt = blockIdx.x;
    const int h  = blockIdx.y;
    const int kvh = h >> 2;
    const int tid = threadIdx.x;
    const int w = tid >> 5;
    const int lane = tid & 31;
    const int g = lane >> 2;
    const int c = lane & 3;
    const int q0 = qt * 64;

    uint32_t* Qs = fsm + FL_QS;
    uint32_t* Ks = fsm + FL_KS;
    uint32_t* Vs = fsm + FL_VS;
    uint32_t* Ps = fsm + FL_PS + w * 16 * QPD;  // per-warp 16x64

    // Load Q tile (scaled), convert to tf32. 64x64 floats / 128 thr = 8 float4.
#pragma unroll
    for (int i = 0; i < 8; i++) {
        int lin = tid + 128 * i;
        int r  = lin >> 4;
        int d4 = (lin & 15) << 2;
        float4 v = *(const float4*)&Q[(size_t)(q0 + r) * DIM + h * HD + d4];
        Qs[r * QPD + d4 + 0] = f2tf32(v.x * 0.125f);
        Qs[r * QPD + d4 + 1] = f2tf32(v.y * 0.125f);
        Qs[r * QPD + d4 + 2] = f2tf32(v.z * 0.125f);
        Qs[r * QPD + d4 + 3] = f2tf32(v.w * 0.125f);
    }

    float m0 = -1e30f, m1 = -1e30f, l0 = 0.f, l1 = 0.f;
    float oacc[8][4] = {};

    for (int kt = 0; kt <= qt; kt++) {
        const int k0 = kt * 64;
        __syncthreads();   // prior iter done with Ks/Vs (and Q loaded, iter 0)

#pragma unroll
        for (int i = 0; i < 8; i++) {
            int lin = tid + 128 * i;
            int r  = lin >> 4;
            int d4 = (lin & 15) << 2;
            float4 kv = *(const float4*)&K[(size_t)(k0 + r) * KVDIM + kvh * HD + d4];
            Ks[r * QPD + d4 + 0] = f2tf32(kv.x);
            Ks[r * QPD + d4 + 1] = f2tf32(kv.y);
            Ks[r * QPD + d4 + 2] = f2tf32(kv.z);
            Ks[r * QPD + d4 + 3] = f2tf32(kv.w);
            float4 vv = *(const float4*)&V[(size_t)(k0 + r) * KVDIM + kvh * HD + d4];
            Vs[r * VPD + d4 + 0] = f2tf32(vv.x);
            Vs[r * VPD + d4 + 1] = f2tf32(vv.y);
            Vs[r * VPD + d4 + 2] = f2tf32(vv.z);
            Vs[r * VPD + d4 + 3] = f2tf32(vv.w);
        }
        __syncthreads();

        // S = Q K^T : warp computes 16x64.
        float s[8][4] = {};
#pragma unroll
        for (int kk = 0; kk < 8; kk++) {
            uint32_t a[4];
            int qb = w * 16;
            a[0] = Qs[(qb + g) * QPD + kk * 8 + c];
            a[1] = Qs[(qb + g + 8) * QPD + kk * 8 + c];
            a[2] = Qs[(qb + g) * QPD + kk * 8 + c + 4];
            a[3] = Qs[(qb + g + 8) * QPD + kk * 8 + c + 4];
#pragma unroll
            for (int nt = 0; nt < 8; nt++) {
                uint32_t b[2];
                b[0] = Ks[(nt * 8 + g) * QPD + kk * 8 + c];
                b[1] = Ks[(nt * 8 + g) * QPD + kk * 8 + c + 4];
                mma_tf32(s[nt], a, b);
            }
        }

        // Causal mask on diagonal tile.
        if (kt == qt) {
            int r0 = w * 16 + g, r1 = r0 + 8;
#pragma unroll
            for (int nt = 0; nt < 8; nt++) {
                int col = nt * 8 + 2 * c;
                if (col     > r0) s[nt][0] = -1e30f;
                if (col + 1 > r0) s[nt][1] = -1e30f;
                if (col     > r1) s[nt][2] = -1e30f;
                if (col + 1 > r1) s[nt][3] = -1e30f;
            }
        }

        // Online softmax (rows g and g+8; row spread over lane quad).
        float mx0 = -1e30f, mx1 = -1e30f;
#pragma unroll
        for (int nt = 0; nt < 8; nt++) {
            mx0 = fmaxf(mx0, fmaxf(s[nt][0], s[nt][1]));
            mx1 = fmaxf(mx1, fmaxf(s[nt][2], s[nt][3]));
        }
        mx0 = fmaxf(mx0, __shfl_xor_sync(0xffffffffu, mx0, 1));
        mx0 = fmaxf(mx0, __shfl_xor_sync(0xffffffffu, mx0, 2));
        mx1 = fmaxf(mx1, __shfl_xor_sync(0xffffffffu, mx1, 1));
        mx1 = fmaxf(mx1, __shfl_xor_sync(0xffffffffu, mx1, 2));

        float mn0 = fmaxf(m0, mx0), mn1 = fmaxf(m1, mx1);
        float al0 = __expf(m0 - mn0), al1 = __expf(m1 - mn1);
        float sum0 = 0.f, sum1 = 0.f;
#pragma unroll
        for (int nt = 0; nt < 8; nt++) {
            s[nt][0] = __expf(s[nt][0] - mn0);
            s[nt][1] = __expf(s[nt][1] - mn0);
            s[nt][2] = __expf(s[nt][2] - mn1);
            s[nt][3] = __expf(s[nt][3] - mn1);
            sum0 += s[nt][0] + s[nt][1];
            sum1 += s[nt][2] + s[nt][3];
        }
        sum0 += __shfl_xor_sync(0xffffffffu, sum0, 1);
        sum0 += __shfl_xor_sync(0xffffffffu, sum0, 2);
        sum1 += __shfl_xor_sync(0xffffffffu, sum1, 1);
        sum1 += __shfl_xor_sync(0xffffffffu, sum1, 2);
        l0 = l0 * al0 + sum0;  m0 = mn0;
        l1 = l1 * al1 + sum1;  m1 = mn1;
#pragma unroll
        for (int nt = 0; nt < 8; nt++) {
            oacc[nt][0] *= al0; oacc[nt][1] *= al0;
            oacc[nt][2] *= al1; oacc[nt][3] *= al1;
        }

        // P -> smem (tf32), re-fragment as A operand. Per-warp region.
#pragma unroll
        for (int nt = 0; nt < 8; nt++) {
            Ps[g * QPD + nt * 8 + 2 * c]           = f2tf32(s[nt][0]);
            Ps[g * QPD + nt * 8 + 2 * c + 1]       = f2tf32(s[nt][1]);
            Ps[(g + 8) * QPD + nt * 8 + 2 * c]     = f2tf32(s[nt][2]);
            Ps[(g + 8) * QPD + nt * 8 + 2 * c + 1] = f2tf32(s[nt][3]);
        }
        __syncwarp();

        // O += P V : 16x64 += 16x64 @ 64x64.
#pragma unroll
        for (int kk = 0; kk < 8; kk++) {
            uint32_t a[4];
            a[0] = Ps[g * QPD + kk * 8 + c];
            a[1] = Ps[(g + 8) * QPD + kk * 8 + c];
            a[2] = Ps[g * QPD + kk * 8 + c + 4];
            a[3] = Ps[(g + 8) * QPD + kk * 8 + c + 4];
#pragma unroll
            for (int nt = 0; nt < 8; nt++) {
                uint32_t b[2];
                b[0] = Vs[(kk * 8 + c) * VPD + nt * 8 + g];
                b[1] = Vs[(kk * 8 + c + 4) * VPD + nt * 8 + g];
                mma_tf32(oacc[nt], a, b);
            }
        }
        __syncwarp();  // P reads done before next iteration's P writes
    }

    // Normalize and write out.
    float inv0 = 1.f / l0, inv1 = 1.f / l1;
    int r0 = q0 + w * 16 + g;
#pragma unroll
    for (int nt = 0; nt < 8; nt++) {
        int col = h * HD + nt * 8 + 2 * c;
        *(float2*)&O[(size_t)r0 * DIM + col] =
            make_float2(oacc[nt][0] * inv0, oacc[nt][1] * inv0);
        *(float2*)&O[(size_t)(r0 + 8) * DIM + col] =
            make_float2(oacc[nt][2] * inv1, oacc[nt][3] * inv1);
    }
}

// ---------------------------------------------------------------------------
// Launch
// ---------------------------------------------------------------------------
extern "C" void kernel_launch(void* const* d_in, const int* in_sizes, int n_in,
                              void* d_out, int out_size) {
    const float* x  = (const float*)d_in[0];
    const float* fc = (const float*)d_in[1];
    const float* fs = (const float*)d_in[2];
    const float* wq = (const float*)d_in[3];
    const float* wk = (const float*)d_in[4];
    const float* wv = (const float*)d_in[5];
    const float* wo = (const float*)d_in[6];
    float* out = (float*)d_out;

    static float *pq = nullptr, *pk = nullptr, *pv = nullptr, *pa = nullptr;
    if (!pq) {
        cudaGetSymbolAddress((void**)&pq, g_q);
        cudaGetSymbolAddress((void**)&pk, g_k);
        cudaGetSymbolAddress((void**)&pv, g_v);
        cudaGetSymbolAddress((void**)&pa, g_attn);
        cudaFuncSetAttribute(flash_tf32,
                             cudaFuncAttributeMaxDynamicSharedMemorySize,
                             FLASH_SMEM);
    }

    dim3 blk(256);
    gemm_tf32<<<dim3(DIM / GBN,   SEQ / GBM), blk>>>(x, wq, pq, SEQ, DIM,   DIM);
    gemm_tf32<<<dim3(KVDIM / GBN, SEQ / GBM), blk>>>(x, wk, pk, SEQ, KVDIM, DIM);
    gemm_tf32<<<dim3(KVDIM / GBN, SEQ / GBM), blk>>>(x, wv, pv, SEQ, KVDIM, DIM);

    rope_kernel<<<(SEQ * (DIM / 2)   + 255) / 256, 256>>>(pq, fc, fs, DIM,   SEQ * (DIM / 2));
    rope_kernel<<<(SEQ * (KVDIM / 2) + 255) / 256, 256>>>(pk, fc, fs, KVDIM, SEQ * (KVDIM / 2));

    flash_tf32<<<dim3(SEQ / 64, NHEADS), dim3(128), FLASH_SMEM>>>(pq, pk, pv, pa);

    gemm_tf32<<<dim3(DIM / GBN, SEQ / GBM), blk>>>(pa, wo, out, SEQ, DIM, DIM);
}

// round 6
// speedup vs baseline: 4.0163x; 1.3928x over previous
#include <cuda_runtime.h>
#include <cuda_fp16.h>
#include <stdint.h>
#include <math.h>

#define SEQ     4096
#define DIM     1024
#define NHEADS  16
#define NKV     4
#define HD      64
#define KVDIM   256

// ---------------------------------------------------------------------------
// Scratch (device globals; cudaMalloc forbidden)
// ---------------------------------------------------------------------------
__device__ float g_q[SEQ * DIM];
__device__ float g_k[SEQ * KVDIM];
__device__ float g_v[SEQ * KVDIM];
__device__ float g_attn[SEQ * DIM];

// ---------------------------------------------------------------------------
// Helpers
// ---------------------------------------------------------------------------
__device__ __forceinline__ uint32_t pack_h2(float a, float b) {
    __half2 h = __floats2half2_rn(a, b);
    return *(uint32_t*)&h;
}
__device__ __forceinline__ uint32_t smem_u32(const void* p) {
    uint32_t a;
    asm("{ .reg .u64 t; cvta.to.shared.u64 t, %1; cvt.u32.u64 %0, t; }"
        : "=r"(a) : "l"(p));
    return a;
}
// m16n8k16 f16 mma, fp32 accum
__device__ __forceinline__ void mma_f16(float c[4], const uint32_t a[4],
                                        const uint32_t b[2]) {
    asm volatile(
        "mma.sync.aligned.m16n8k16.row.col.f32.f16.f16.f32 "
        "{%0,%1,%2,%3},{%4,%5,%6,%7},{%8,%9},{%0,%1,%2,%3};"
        : "+f"(c[0]), "+f"(c[1]), "+f"(c[2]), "+f"(c[3])
        : "r"(a[0]), "r"(a[1]), "r"(a[2]), "r"(a[3]), "r"(b[0]), "r"(b[1]));
}
__device__ __forceinline__ void ldsm_x4_trans(uint32_t& r0, uint32_t& r1,
                                              uint32_t& r2, uint32_t& r3,
                                              uint32_t addr) {
    asm volatile(
        "ldmatrix.sync.aligned.m8n8.x4.trans.shared.b16 {%0,%1,%2,%3}, [%4];"
        : "=r"(r0), "=r"(r1), "=r"(r2), "=r"(r3) : "r"(addr));
}

// ---------------------------------------------------------------------------
// f16 GEMM: C[M,N] = A[M,K] @ B[N,K]^T (row-major A, B). fp32 accumulate.
// BM=128, BN=64, BK=32, 256 threads (8 warps: 4m x 2n), warp tile 32x32.
// ---------------------------------------------------------------------------
#define GAP 40   // half pitch

__global__ __launch_bounds__(256) void gemm_f16(const float* __restrict__ A,
                                                const float* __restrict__ B,
                                                float* __restrict__ C,
                                                int M, int N, int K) {
    __shared__ __align__(16) __half As[128 * GAP];
    __shared__ __align__(16) __half Bs[64 * GAP];

    const int tid = threadIdx.x;
    const int wid = tid >> 5;
    const int lane = tid & 31;
    const int g = lane >> 2;
    const int c = lane & 3;
    const int wm = wid >> 1;
    const int wn = wid & 1;
    const int row0 = blockIdx.y * 128;
    const int col0 = blockIdx.x * 64;

    float acc[2][4][4] = {};

    for (int k0 = 0; k0 < K; k0 += 32) {
#pragma unroll
        for (int i = 0; i < 4; i++) {
            int lin = tid + 256 * i;
            int r  = lin >> 3;
            int kq = (lin & 7) << 2;
            float4 v = *(const float4*)&A[(size_t)(row0 + r) * K + k0 + kq];
            *(uint2*)&As[r * GAP + kq] =
                make_uint2(pack_h2(v.x, v.y), pack_h2(v.z, v.w));
        }
#pragma unroll
        for (int i = 0; i < 2; i++) {
            int lin = tid + 256 * i;
            int r  = lin >> 3;
            int kq = (lin & 7) << 2;
            float4 v = *(const float4*)&B[(size_t)(col0 + r) * K + k0 + kq];
            *(uint2*)&Bs[r * GAP + kq] =
                make_uint2(pack_h2(v.x, v.y), pack_h2(v.z, v.w));
        }
        __syncthreads();

#pragma unroll
        for (int kk = 0; kk < 2; kk++) {
            uint32_t a[2][4];
#pragma unroll
            for (int mt = 0; mt < 2; mt++) {
                int mb = wm * 32 + mt * 16;
                a[mt][0] = *(uint32_t*)&As[(mb + g)     * GAP + kk * 16 + 2 * c];
                a[mt][1] = *(uint32_t*)&As[(mb + g + 8) * GAP + kk * 16 + 2 * c];
                a[mt][2] = *(uint32_t*)&As[(mb + g)     * GAP + kk * 16 + 2 * c + 8];
                a[mt][3] = *(uint32_t*)&As[(mb + g + 8) * GAP + kk * 16 + 2 * c + 8];
            }
#pragma unroll
            for (int nt = 0; nt < 4; nt++) {
                int nb = wn * 32 + nt * 8;
                uint32_t b[2];
                b[0] = *(uint32_t*)&Bs[(nb + g) * GAP + kk * 16 + 2 * c];
                b[1] = *(uint32_t*)&Bs[(nb + g) * GAP + kk * 16 + 2 * c + 8];
#pragma unroll
                for (int mt = 0; mt < 2; mt++)
                    mma_f16(acc[mt][nt], a[mt], b);
            }
        }
        __syncthreads();
    }

#pragma unroll
    for (int mt = 0; mt < 2; mt++) {
#pragma unroll
        for (int nt = 0; nt < 4; nt++) {
            int r = row0 + wm * 32 + mt * 16 + g;
            int col = col0 + wn * 32 + nt * 8 + 2 * c;
            *(float2*)&C[(size_t)r * N + col] =
                make_float2(acc[mt][nt][0], acc[mt][nt][1]);
            *(float2*)&C[(size_t)(r + 8) * N + col] =
                make_float2(acc[mt][nt][2], acc[mt][nt][3]);
        }
    }
}

// ---------------------------------------------------------------------------
// RoPE (in place)
// ---------------------------------------------------------------------------
__global__ void rope_kernel(float* __restrict__ buf,
                            const float* __restrict__ cosb,
                            const float* __restrict__ sinb,
                            int ncols, int total_pairs) {
    int idx = blockIdx.x * blockDim.x + threadIdx.x;
    if (idx >= total_pairs) return;
    int ppr = ncols >> 1;
    int s = idx / ppr;
    int p = idx - s * ppr;
    int i = p & 31;
    int col = ((p >> 5) << 6) + (i << 1);
    float cth = cosb[s * 32 + i];
    float sth = sinb[s * 32 + i];
    float* base = &buf[(size_t)s * ncols + col];
    float xr = base[0], xi = base[1];
    base[0] = xr * cth - xi * sth;
    base[1] = xr * sth + xi * cth;
}

// ---------------------------------------------------------------------------
// Flash attention, f16 m16n8k16, causal, GQA.
// 128 threads (4 warps); q-tile 64, k-tile 64. Warp w owns q rows [16w,16w+16).
// Q/K/P frags via direct half2 LDS (pitch 72: bank 4g+c, conflict-free).
// V B-frags via ldmatrix.x4.trans on row-major V (144B rows, conflict-free).
// ---------------------------------------------------------------------------
#define FP 72   // half pitch

__global__ __launch_bounds__(128) void flash_f16(const float* __restrict__ Q,
                                                 const float* __restrict__ K,
                                                 const float* __restrict__ V,
                                                 float* __restrict__ O) {
    __shared__ __align__(16) __half Qs[64 * FP];
    __shared__ __align__(16) __half Ks[64 * FP];
    __shared__ __align__(16) __half Vs[64 * FP];
    __shared__ __align__(16) __half Pall[64 * FP];

    const int qt = blockIdx.x;
    const int h  = blockIdx.y;
    const int kvh = h >> 2;
    const int tid = threadIdx.x;
    const int w = tid >> 5;
    const int lane = tid & 31;
    const int g = lane >> 2;
    const int c = lane & 3;
    const int q0 = qt * 64;

    __half* Ps = Pall + w * 16 * FP;
    const uint32_t vbase = smem_u32(Vs);
    const int lm_row = lane & 15;         // k-row within 16-chunk
    const int lm_cs  = (lane >> 4) & 1;   // n lo/hi 8 select

#pragma unroll
    for (int i = 0; i < 8; i++) {
        int lin = tid + 128 * i;
        int r  = lin >> 4;
        int d4 = (lin & 15) << 2;
        float4 v = *(const float4*)&Q[(size_t)(q0 + r) * DIM + h * HD + d4];
        *(uint2*)&Qs[r * FP + d4] =
            make_uint2(pack_h2(v.x * 0.125f, v.y * 0.125f),
                       pack_h2(v.z * 0.125f, v.w * 0.125f));
    }

    float m0 = -1e30f, m1 = -1e30f, l0 = 0.f, l1 = 0.f;
    float oacc[8][4] = {};

    for (int kt = 0; kt <= qt; kt++) {
        const int k0 = kt * 64;
        __syncthreads();

#pragma unroll
        for (int i = 0; i < 8; i++) {
            int lin = tid + 128 * i;
            int r  = lin >> 4;
            int d4 = (lin & 15) << 2;
            float4 kv = *(const float4*)&K[(size_t)(k0 + r) * KVDIM + kvh * HD + d4];
            *(uint2*)&Ks[r * FP + d4] =
                make_uint2(pack_h2(kv.x, kv.y), pack_h2(kv.z, kv.w));
            float4 vv = *(const float4*)&V[(size_t)(k0 + r) * KVDIM + kvh * HD + d4];
            *(uint2*)&Vs[r * FP + d4] =
                make_uint2(pack_h2(vv.x, vv.y), pack_h2(vv.z, vv.w));
        }
        __syncthreads();

        float s[8][4] = {};
        const int qb = w * 16;
#pragma unroll
        for (int kk = 0; kk < 4; kk++) {
            uint32_t a[4];
            a[0] = *(uint32_t*)&Qs[(qb + g)     * FP + kk * 16 + 2 * c];
            a[1] = *(uint32_t*)&Qs[(qb + g + 8) * FP + kk * 16 + 2 * c];
            a[2] = *(uint32_t*)&Qs[(qb + g)     * FP + kk * 16 + 2 * c + 8];
            a[3] = *(uint32_t*)&Qs[(qb + g + 8) * FP + kk * 16 + 2 * c + 8];
#pragma unroll
            for (int nt = 0; nt < 8; nt++) {
                uint32_t b[2];
                b[0] = *(uint32_t*)&Ks[(nt * 8 + g) * FP + kk * 16 + 2 * c];
                b[1] = *(uint32_t*)&Ks[(nt * 8 + g) * FP + kk * 16 + 2 * c + 8];
                mma_f16(s[nt], a, b);
            }
        }

        if (kt == qt) {
            int r0 = w * 16 + g, r1 = r0 + 8;
#pragma unroll
            for (int nt = 0; nt < 8; nt++) {
                int col = nt * 8 + 2 * c;
                if (col     > r0) s[nt][0] = -1e30f;
                if (col + 1 > r0) s[nt][1] = -1e30f;
                if (col     > r1) s[nt][2] = -1e30f;
                if (col + 1 > r1) s[nt][3] = -1e30f;
            }
        }

        float mx0 = -1e30f, mx1 = -1e30f;
#pragma unroll
        for (int nt = 0; nt < 8; nt++) {
            mx0 = fmaxf(mx0, fmaxf(s[nt][0], s[nt][1]));
            mx1 = fmaxf(mx1, fmaxf(s[nt][2], s[nt][3]));
        }
        mx0 = fmaxf(mx0, __shfl_xor_sync(0xffffffffu, mx0, 1));
        mx0 = fmaxf(mx0, __shfl_xor_sync(0xffffffffu, mx0, 2));
        mx1 = fmaxf(mx1, __shfl_xor_sync(0xffffffffu, mx1, 1));
        mx1 = fmaxf(mx1, __shfl_xor_sync(0xffffffffu, mx1, 2));

        float mn0 = fmaxf(m0, mx0), mn1 = fmaxf(m1, mx1);
        float al0 = __expf(m0 - mn0), al1 = __expf(m1 - mn1);
        float sum0 = 0.f, sum1 = 0.f;
#pragma unroll
        for (int nt = 0; nt < 8; nt++) {
            s[nt][0] = __expf(s[nt][0] - mn0);
            s[nt][1] = __expf(s[nt][1] - mn0);
            s[nt][2] = __expf(s[nt][2] - mn1);
            s[nt][3] = __expf(s[nt][3] - mn1);
            sum0 += s[nt][0] + s[nt][1];
            sum1 += s[nt][2] + s[nt][3];
        }
        sum0 += __shfl_xor_sync(0xffffffffu, sum0, 1);
        sum0 += __shfl_xor_sync(0xffffffffu, sum0, 2);
        sum1 += __shfl_xor_sync(0xffffffffu, sum1, 1);
        sum1 += __shfl_xor_sync(0xffffffffu, sum1, 2);
        l0 = l0 * al0 + sum0;  m0 = mn0;
        l1 = l1 * al1 + sum1;  m1 = mn1;
#pragma unroll
        for (int nt = 0; nt < 8; nt++) {
            oacc[nt][0] *= al0; oacc[nt][1] *= al0;
            oacc[nt][2] *= al1; oacc[nt][3] *= al1;
        }

#pragma unroll
        for (int nt = 0; nt < 8; nt++) {
            *(uint32_t*)&Ps[g       * FP + nt * 8 + 2 * c] = pack_h2(s[nt][0], s[nt][1]);
            *(uint32_t*)&Ps[(g + 8) * FP + nt * 8 + 2 * c] = pack_h2(s[nt][2], s[nt][3]);
        }
        __syncwarp();

#pragma unroll
        for (int kk = 0; kk < 4; kk++) {
            uint32_t a[4];
            a[0] = *(uint32_t*)&Ps[g       * FP + kk * 16 + 2 * c];
            a[1] = *(uint32_t*)&Ps[(g + 8) * FP + kk * 16 + 2 * c];
            a[2] = *(uint32_t*)&Ps[g       * FP + kk * 16 + 2 * c + 8];
            a[3] = *(uint32_t*)&Ps[(g + 8) * FP + kk * 16 + 2 * c + 8];
#pragma unroll
            for (int ntp = 0; ntp < 4; ntp++) {
                uint32_t addr = vbase +
                    (uint32_t)(kk * 16 + lm_row) * (FP * 2) +
                    (uint32_t)(16 * ntp + 8 * lm_cs) * 2;
                uint32_t b0, b1, b2, b3;
                ldsm_x4_trans(b0, b1, b2, b3, addr);
                uint32_t blo[2] = {b0, b1}, bhi[2] = {b2, b3};
                mma_f16(oacc[2 * ntp],     a, blo);
                mma_f16(oacc[2 * ntp + 1], a, bhi);
            }
        }
        __syncwarp();
    }

    float inv0 = 1.f / l0, inv1 = 1.f / l1;
    int r0 = q0 + w * 16 + g;
#pragma unroll
    for (int nt = 0; nt < 8; nt++) {
        int col = h * HD + nt * 8 + 2 * c;
        *(float2*)&O[(size_t)r0 * DIM + col] =
            make_float2(oacc[nt][0] * inv0, oacc[nt][1] * inv0);
        *(float2*)&O[(size_t)(r0 + 8) * DIM + col] =
            make_float2(oacc[nt][2] * inv1, oacc[nt][3] * inv1);
    }
}

// ---------------------------------------------------------------------------
// Launch
// ---------------------------------------------------------------------------
extern "C" void kernel_launch(void* const* d_in, const int* in_sizes, int n_in,
                              void* d_out, int out_size) {
    const float* x  = (const float*)d_in[0];
    const float* fc = (const float*)d_in[1];
    const float* fs = (const float*)d_in[2];
    const float* wq = (const float*)d_in[3];
    const float* wk = (const float*)d_in[4];
    const float* wv = (const float*)d_in[5];
    const float* wo = (const float*)d_in[6];
    float* out = (float*)d_out;

    static float *pq = nullptr, *pk = nullptr, *pv = nullptr, *pa = nullptr;
    if (!pq) {
        cudaGetSymbolAddress((void**)&pq, g_q);
        cudaGetSymbolAddress((void**)&pk, g_k);
        cudaGetSymbolAddress((void**)&pv, g_v);
        cudaGetSymbolAddress((void**)&pa, g_attn);
    }

    dim3 blk(256);
    gemm_f16<<<dim3(DIM / 64,   SEQ / 128), blk>>>(x, wq, pq, SEQ, DIM,   DIM);
    gemm_f16<<<dim3(KVDIM / 64, SEQ / 128), blk>>>(x, wk, pk, SEQ, KVDIM, DIM);
    gemm_f16<<<dim3(KVDIM / 64, SEQ / 128), blk>>>(x, wv, pv, SEQ, KVDIM, DIM);

    rope_kernel<<<(SEQ * (DIM / 2)   + 255) / 256, 256>>>(pq, fc, fs, DIM,   SEQ * (DIM / 2));
    rope_kernel<<<(SEQ * (KVDIM / 2) + 255) / 256, 256>>>(pk, fc, fs, KVDIM, SEQ * (KVDIM / 2));

    flash_f16<<<dim3(SEQ / 64, NHEADS), dim3(128)>>>(pq, pk, pv, pa);

    gemm_f16<<<dim3(DIM / 64, SEQ / 128), blk>>>(pa, wo, out, SEQ, DIM, DIM);
}

// round 9
// speedup vs baseline: 4.6860x; 1.1667x over previous
#include <cuda_runtime.h>
#include <cuda_fp16.h>
#include <stdint.h>
#include <math.h>

#define SEQ     4096
#define DIM     1024
#define NHEADS  16
#define NKV     4
#define HD      64
#define KVDIM   256

// ---------------------------------------------------------------------------
// Scratch (device globals; cudaMalloc forbidden) — fp16
// ---------------------------------------------------------------------------
__device__ __half g_qh[SEQ * DIM];
__device__ __half g_kh[SEQ * KVDIM];
__device__ __half g_vh[SEQ * KVDIM];
__device__ __half g_ah[SEQ * DIM];

// ---------------------------------------------------------------------------
// Helpers
// ---------------------------------------------------------------------------
__device__ __forceinline__ uint32_t pack_h2(float a, float b) {
    __half2 h = __floats2half2_rn(a, b);
    return *(uint32_t*)&h;
}
__device__ __forceinline__ uint32_t smem_u32(const void* p) {
    uint32_t a;
    asm("{ .reg .u64 t; cvta.to.shared.u64 t, %1; cvt.u32.u64 %0, t; }"
        : "=r"(a) : "l"(p));
    return a;
}
__device__ __forceinline__ void mma_f16(float c[4], const uint32_t a[4],
                                        const uint32_t b[2]) {
    asm volatile(
        "mma.sync.aligned.m16n8k16.row.col.f32.f16.f16.f32 "
        "{%0,%1,%2,%3},{%4,%5,%6,%7},{%8,%9},{%0,%1,%2,%3};"
        : "+f"(c[0]), "+f"(c[1]), "+f"(c[2]), "+f"(c[3])
        : "r"(a[0]), "r"(a[1]), "r"(a[2]), "r"(a[3]), "r"(b[0]), "r"(b[1]));
}
__device__ __forceinline__ void ldsm_x4_trans(uint32_t& r0, uint32_t& r1,
                                              uint32_t& r2, uint32_t& r3,
                                              uint32_t addr) {
    asm volatile(
        "ldmatrix.sync.aligned.m8n8.x4.trans.shared.b16 {%0,%1,%2,%3}, [%4];"
        : "=r"(r0), "=r"(r1), "=r"(r2), "=r"(r3) : "r"(addr));
}

// ---------------------------------------------------------------------------
// f16 GEMM: C[M,N] = alpha * A[M,K] @ B[N,K]^T, optional fused RoPE epilogue.
// A: float or half (template). B: float weights. C: half or float (template).
// BM=128, BN=64, BK=32, 256 threads (8 warps 4m x 2n), warp tile 32x32.
// Pitch 40 halves (>= BK=32; fragment bank = 4g + c, conflict-free).
// ---------------------------------------------------------------------------
#define GAP 40

template <bool ROPE, bool AHALF, bool CHALF>
__global__ __launch_bounds__(256) void gemm_k(const void* __restrict__ Ap,
                                              const float* __restrict__ B,
                                              void* __restrict__ Cp,
                                              int M, int N, int K,
                                              const float* __restrict__ cosb,
                                              const float* __restrict__ sinb,
                                              float alpha) {
    __shared__ __align__(16) __half As[128 * GAP];
    __shared__ __align__(16) __half Bs[64 * GAP];

    const int tid = threadIdx.x;
    const int wid = tid >> 5;
    const int lane = tid & 31;
    const int g = lane >> 2;
    const int c = lane & 3;
    const int wm = wid >> 1;
    const int wn = wid & 1;
    const int row0 = blockIdx.y * 128;
    const int col0 = blockIdx.x * 64;

    float acc[2][4][4] = {};

    for (int k0 = 0; k0 < K; k0 += 32) {
        if (AHALF) {
            const __half* A = (const __half*)Ap;
#pragma unroll
            for (int i = 0; i < 2; i++) {
                int lin = tid + 256 * i;          // 0..511
                int r  = lin >> 2;                // 0..127
                int k8 = (lin & 3) << 3;          // 0,8,16,24
                uint4 v = *(const uint4*)&A[(size_t)(row0 + r) * K + k0 + k8];
                *(uint4*)&As[r * GAP + k8] = v;
            }
        } else {
            const float* A = (const float*)Ap;
#pragma unroll
            for (int i = 0; i < 4; i++) {
                int lin = tid + 256 * i;          // 0..1023
                int r  = lin >> 3;                // 0..127
                int kq = (lin & 7) << 2;          // 0..28
                float4 v = *(const float4*)&A[(size_t)(row0 + r) * K + k0 + kq];
                *(uint2*)&As[r * GAP + kq] =
                    make_uint2(pack_h2(v.x, v.y), pack_h2(v.z, v.w));
            }
        }
#pragma unroll
        for (int i = 0; i < 2; i++) {
            int lin = tid + 256 * i;
            int r  = lin >> 3;                    // 0..63
            int kq = (lin & 7) << 2;
            float4 v = *(const float4*)&B[(size_t)(col0 + r) * K + k0 + kq];
            *(uint2*)&Bs[r * GAP + kq] =
                make_uint2(pack_h2(v.x, v.y), pack_h2(v.z, v.w));
        }
        __syncthreads();

#pragma unroll
        for (int kk = 0; kk < 2; kk++) {
            uint32_t a[2][4];
#pragma unroll
            for (int mt = 0; mt < 2; mt++) {
                int mb = wm * 32 + mt * 16;
                a[mt][0] = *(uint32_t*)&As[(mb + g)     * GAP + kk * 16 + 2 * c];
                a[mt][1] = *(uint32_t*)&As[(mb + g + 8) * GAP + kk * 16 + 2 * c];
                a[mt][2] = *(uint32_t*)&As[(mb + g)     * GAP + kk * 16 + 2 * c + 8];
                a[mt][3] = *(uint32_t*)&As[(mb + g + 8) * GAP + kk * 16 + 2 * c + 8];
            }
#pragma unroll
            for (int nt = 0; nt < 4; nt++) {
                int nb = wn * 32 + nt * 8;
                uint32_t b[2];
                b[0] = *(uint32_t*)&Bs[(nb + g) * GAP + kk * 16 + 2 * c];
                b[1] = *(uint32_t*)&Bs[(nb + g) * GAP + kk * 16 + 2 * c + 8];
#pragma unroll
                for (int mt = 0; mt < 2; mt++)
                    mma_f16(acc[mt][nt], a[mt], b);
            }
        }
        __syncthreads();
    }

    // Epilogue: optional scale + RoPE rotation, then store (half or float).
#pragma unroll
    for (int mt = 0; mt < 2; mt++) {
#pragma unroll
        for (int nt = 0; nt < 4; nt++) {
            int r = row0 + wm * 32 + mt * 16 + g;
            int col = col0 + wn * 32 + nt * 8 + 2 * c;   // even
            float v0 = acc[mt][nt][0] * alpha;
            float v1 = acc[mt][nt][1] * alpha;
            float v2 = acc[mt][nt][2] * alpha;
            float v3 = acc[mt][nt][3] * alpha;
            if (ROPE) {
                int i = (col & 63) >> 1;
                float c0 = cosb[r * 32 + i],        s0 = sinb[r * 32 + i];
                float c1 = cosb[(r + 8) * 32 + i],  s1 = sinb[(r + 8) * 32 + i];
                float t0 = v0 * c0 - v1 * s0;
                float t1 = v0 * s0 + v1 * c0;
                float t2 = v2 * c1 - v3 * s1;
                float t3 = v2 * s1 + v3 * c1;
                v0 = t0; v1 = t1; v2 = t2; v3 = t3;
            }
            if (CHALF) {
                __half* C = (__half*)Cp;
                *(uint32_t*)&C[(size_t)r * N + col]       = pack_h2(v0, v1);
                *(uint32_t*)&C[(size_t)(r + 8) * N + col] = pack_h2(v2, v3);
            } else {
                float* C = (float*)Cp;
                *(float2*)&C[(size_t)r * N + col]       = make_float2(v0, v1);
                *(float2*)&C[(size_t)(r + 8) * N + col] = make_float2(v2, v3);
            }
        }
    }
}

// ---------------------------------------------------------------------------
// Flash attention, f16 m16n8k16, causal, GQA. fp16 in, fp16 out.
// 256 threads (8 warps); q-tile 128 rows, k-tile 64. Warp w: rows [16w,16w+16).
// Pitch 72 halves (>= 64-wide tiles; bank = 4g + c, conflict-free; ldmatrix
// phases cover all 32 banks). Dynamic smem (55296 B).
// ---------------------------------------------------------------------------
#define FP 72
#define FL_QS 0
#define FL_KS (128 * FP)
#define FL_VS (FL_KS + 64 * FP)
#define FL_PS (FL_VS + 64 * FP)
#define FLASH_SMEM ((FL_PS + 128 * FP) * 2)   // halves -> bytes

extern __shared__ __half fsm[];

__global__ __launch_bounds__(256) void flash_f16(const __half* __restrict__ Q,
                                                 const __half* __restrict__ K,
                                                 const __half* __restrict__ V,
                                                 __half* __restrict__ O) {
    __half* Qs = fsm + FL_QS;
    __half* Ks = fsm + FL_KS;
    __half* Vs = fsm + FL_VS;

    const int qt = gridDim.x - 1 - blockIdx.x;   // big tiles first
    const int h  = blockIdx.y;
    const int kvh = h >> 2;
    const int tid = threadIdx.x;
    const int w = tid >> 5;
    const int lane = tid & 31;
    const int g = lane >> 2;
    const int c = lane & 3;
    const int q0 = qt * 128;
    const int qb = w * 16;              // warp's row base within tile

    __half* Ps = fsm + FL_PS + w * 16 * FP;
    const uint32_t vbase = smem_u32(Vs);
    const int lm_row = lane & 15;
    const int lm_cs  = (lane >> 4) & 1;

    // Load Q tile (pre-scaled + rope'd by projection). 128x64 halves.
#pragma unroll
    for (int i = 0; i < 4; i++) {
        int lin = tid + 256 * i;        // 0..1023
        int r  = lin >> 3;              // 0..127
        int d8 = (lin & 7) << 3;        // 0..56
        uint4 v = *(const uint4*)&Q[(size_t)(q0 + r) * DIM + h * HD + d8];
        *(uint4*)&Qs[r * FP + d8] = v;
    }

    float m0 = -1e30f, m1 = -1e30f, l0 = 0.f, l1 = 0.f;
    float oacc[8][4] = {};

    const int NT = 2 * qt + 2;          // k-tiles
    for (int kt = 0; kt < NT; kt++) {
        const int k0 = kt * 64;
        __syncthreads();

        // Load K and V tiles (64x64 halves each).
#pragma unroll
        for (int i = 0; i < 2; i++) {
            int lin = tid + 256 * i;    // 0..511
            int r  = lin >> 3;          // 0..63
            int d8 = (lin & 7) << 3;
            *(uint4*)&Ks[r * FP + d8] =
                *(const uint4*)&K[(size_t)(k0 + r) * KVDIM + kvh * HD + d8];
            *(uint4*)&Vs[r * FP + d8] =
                *(const uint4*)&V[(size_t)(k0 + r) * KVDIM + kvh * HD + d8];
        }
        __syncthreads();

        // Warp-uniform skip: tile entirely beyond this warp's last row.
        if (k0 > q0 + qb + 15) continue;

        // S = Q K^T : warp computes 16x64.
        float s[8][4] = {};
#pragma unroll
        for (int kk = 0; kk < 4; kk++) {
            uint32_t a[4];
            a[0] = *(uint32_t*)&Qs[(qb + g)     * FP + kk * 16 + 2 * c];
            a[1] = *(uint32_t*)&Qs[(qb + g + 8) * FP + kk * 16 + 2 * c];
            a[2] = *(uint32_t*)&Qs[(qb + g)     * FP + kk * 16 + 2 * c + 8];
            a[3] = *(uint32_t*)&Qs[(qb + g + 8) * FP + kk * 16 + 2 * c + 8];
#pragma unroll
            for (int nt = 0; nt < 8; nt++) {
                uint32_t b[2];
                b[0] = *(uint32_t*)&Ks[(nt * 8 + g) * FP + kk * 16 + 2 * c];
                b[1] = *(uint32_t*)&Ks[(nt * 8 + g) * FP + kk * 16 + 2 * c + 8];
                mma_f16(s[nt], a, b);
            }
        }

        // Causal mask (only k-tiles crossing the diagonal need it).
        if (kt >= 2 * qt) {
            int r0 = q0 + qb + g, r1 = r0 + 8;
#pragma unroll
            for (int nt = 0; nt < 8; nt++) {
                int col = k0 + nt * 8 + 2 * c;
                if (col     > r0) s[nt][0] = -1e30f;
                if (col + 1 > r0) s[nt][1] = -1e30f;
                if (col     > r1) s[nt][2] = -1e30f;
                if (col + 1 > r1) s[nt][3] = -1e30f;
            }
        }

        // Online softmax.
        float mx0 = -1e30f, mx1 = -1e30f;
#pragma unroll
        for (int nt = 0; nt < 8; nt++) {
            mx0 = fmaxf(mx0, fmaxf(s[nt][0], s[nt][1]));
            mx1 = fmaxf(mx1, fmaxf(s[nt][2], s[nt][3]));
        }
        mx0 = fmaxf(mx0, __shfl_xor_sync(0xffffffffu, mx0, 1));
        mx0 = fmaxf(mx0, __shfl_xor_sync(0xffffffffu, mx0, 2));
        mx1 = fmaxf(mx1, __shfl_xor_sync(0xffffffffu, mx1, 1));
        mx1 = fmaxf(mx1, __shfl_xor_sync(0xffffffffu, mx1, 2));

        float mn0 = fmaxf(m0, mx0), mn1 = fmaxf(m1, mx1);
        float al0 = __expf(m0 - mn0), al1 = __expf(m1 - mn1);
        float sum0 = 0.f, sum1 = 0.f;
#pragma unroll
        for (int nt = 0; nt < 8; nt++) {
            s[nt][0] = __expf(s[nt][0] - mn0);
            s[nt][1] = __expf(s[nt][1] - mn0);
            s[nt][2] = __expf(s[nt][2] - mn1);
            s[nt][3] = __expf(s[nt][3] - mn1);
            sum0 += s[nt][0] + s[nt][1];
            sum1 += s[nt][2] + s[nt][3];
        }
        sum0 += __shfl_xor_sync(0xffffffffu, sum0, 1);
        sum0 += __shfl_xor_sync(0xffffffffu, sum0, 2);
        sum1 += __shfl_xor_sync(0xffffffffu, sum1, 1);
        sum1 += __shfl_xor_sync(0xffffffffu, sum1, 2);
        l0 = l0 * al0 + sum0;  m0 = mn0;
        l1 = l1 * al1 + sum1;  m1 = mn1;
#pragma unroll
        for (int nt = 0; nt < 8; nt++) {
            oacc[nt][0] *= al0; oacc[nt][1] *= al0;
            oacc[nt][2] *= al1; oacc[nt][3] *= al1;
        }

        // P -> per-warp smem (fp16), re-fragment as A operand.
#pragma unroll
        for (int nt = 0; nt < 8; nt++) {
            *(uint32_t*)&Ps[g       * FP + nt * 8 + 2 * c] = pack_h2(s[nt][0], s[nt][1]);
            *(uint32_t*)&Ps[(g + 8) * FP + nt * 8 + 2 * c] = pack_h2(s[nt][2], s[nt][3]);
        }
        __syncwarp();

        // O += P V  (V B-frags via ldmatrix.trans).
#pragma unroll
        for (int kk = 0; kk < 4; kk++) {
            uint32_t a[4];
            a[0] = *(uint32_t*)&Ps[g       * FP + kk * 16 + 2 * c];
            a[1] = *(uint32_t*)&Ps[(g + 8) * FP + kk * 16 + 2 * c];
            a[2] = *(uint32_t*)&Ps[g       * FP + kk * 16 + 2 * c + 8];
            a[3] = *(uint32_t*)&Ps[(g + 8) * FP + kk * 16 + 2 * c + 8];
#pragma unroll
            for (int ntp = 0; ntp < 4; ntp++) {
                uint32_t addr = vbase +
                    (uint32_t)(kk * 16 + lm_row) * (FP * 2) +
                    (uint32_t)(16 * ntp + 8 * lm_cs) * 2;
                uint32_t b0, b1, b2, b3;
                ldsm_x4_trans(b0, b1, b2, b3, addr);
                uint32_t blo[2] = {b0, b1}, bhi[2] = {b2, b3};
                mma_f16(oacc[2 * ntp],     a, blo);
                mma_f16(oacc[2 * ntp + 1], a, bhi);
            }
        }
        __syncwarp();
    }

    // Normalize and write fp16 output.
    float inv0 = 1.f / l0, inv1 = 1.f / l1;
    int r0 = q0 + qb + g;
#pragma unroll
    for (int nt = 0; nt < 8; nt++) {
        int col = h * HD + nt * 8 + 2 * c;
        *(uint32_t*)&O[(size_t)r0 * DIM + col] =
            pack_h2(oacc[nt][0] * inv0, oacc[nt][1] * inv0);
        *(uint32_t*)&O[(size_t)(r0 + 8) * DIM + col] =
            pack_h2(oacc[nt][2] * inv1, oacc[nt][3] * inv1);
    }
}

// ---------------------------------------------------------------------------
// Launch
// ---------------------------------------------------------------------------
extern "C" void kernel_launch(void* const* d_in, const int* in_sizes, int n_in,
                              void* d_out, int out_size) {
    const float* x  = (const float*)d_in[0];
    const float* fc = (const float*)d_in[1];
    const float* fs = (const float*)d_in[2];
    const float* wq = (const float*)d_in[3];
    const float* wk = (const float*)d_in[4];
    const float* wv = (const float*)d_in[5];
    const float* wo = (const float*)d_in[6];
    float* out = (float*)d_out;

    static __half *pq = nullptr, *pk = nullptr, *pv = nullptr, *pa = nullptr;
    if (!pq) {
        cudaGetSymbolAddress((void**)&pq, g_qh);
        cudaGetSymbolAddress((void**)&pk, g_kh);
        cudaGetSymbolAddress((void**)&pv, g_vh);
        cudaGetSymbolAddress((void**)&pa, g_ah);
        cudaFuncSetAttribute(flash_f16,
                             cudaFuncAttributeMaxDynamicSharedMemorySize,
                             FLASH_SMEM);
    }

    dim3 blk(256);
    // Q proj: rope + 1/sqrt(64) scale fused, half out.
    gemm_k<true, false, true><<<dim3(DIM / 64, SEQ / 128), blk>>>(
        x, wq, pq, SEQ, DIM, DIM, fc, fs, 0.125f);
    // K proj: rope fused, half out.
    gemm_k<true, false, true><<<dim3(KVDIM / 64, SEQ / 128), blk>>>(
        x, wk, pk, SEQ, KVDIM, DIM, fc, fs, 1.0f);
    // V proj: half out.
    gemm_k<false, false, true><<<dim3(KVDIM / 64, SEQ / 128), blk>>>(
        x, wv, pv, SEQ, KVDIM, DIM, nullptr, nullptr, 1.0f);

    // Flash attention (fp16 in/out).
    flash_f16<<<dim3(SEQ / 128, NHEADS), blk, FLASH_SMEM>>>(pq, pk, pv, pa);

    // O proj: half A, float out.
    gemm_k<false, true, false><<<dim3(DIM / 64, SEQ / 128), blk>>>(
        pa, wo, out, SEQ, DIM, DIM, nullptr, nullptr, 1.0f);
}

// round 10
// speedup vs baseline: 5.6675x; 1.2094x over previous
#include <cuda_runtime.h>
#include <cuda_fp16.h>
#include <stdint.h>
#include <math.h>

#define SEQ     4096
#define DIM     1024
#define NHEADS  16
#define NKV     4
#define HD      64
#define KVDIM   256

// ---------------------------------------------------------------------------
// Scratch (device globals; cudaMalloc forbidden) — fp16
// ---------------------------------------------------------------------------
__device__ __half g_qh[SEQ * DIM];
__device__ __half g_kh[SEQ * KVDIM];
__device__ __half g_vh[SEQ * KVDIM];
__device__ __half g_ah[SEQ * DIM];
__device__ __half g_xh[SEQ * DIM];
__device__ __half g_wqh[DIM * DIM];
__device__ __half g_wkh[KVDIM * DIM];
__device__ __half g_wvh[KVDIM * DIM];
__device__ __half g_woh[DIM * DIM];

// ---------------------------------------------------------------------------
// Helpers
// ---------------------------------------------------------------------------
__device__ __forceinline__ uint32_t pack_h2(float a, float b) {
    __half2 h = __floats2half2_rn(a, b);
    return *(uint32_t*)&h;
}
__device__ __forceinline__ uint32_t smem_u32(const void* p) {
    uint32_t a;
    asm("{ .reg .u64 t; cvta.to.shared.u64 t, %1; cvt.u32.u64 %0, t; }"
        : "=r"(a) : "l"(p));
    return a;
}
__device__ __forceinline__ void mma_f16(float c[4], const uint32_t a[4],
                                        const uint32_t b[2]) {
    asm volatile(
        "mma.sync.aligned.m16n8k16.row.col.f32.f16.f16.f32 "
        "{%0,%1,%2,%3},{%4,%5,%6,%7},{%8,%9},{%0,%1,%2,%3};"
        : "+f"(c[0]), "+f"(c[1]), "+f"(c[2]), "+f"(c[3])
        : "r"(a[0]), "r"(a[1]), "r"(a[2]), "r"(a[3]), "r"(b[0]), "r"(b[1]));
}
__device__ __forceinline__ void ldsm_x4_trans(uint32_t& r0, uint32_t& r1,
                                              uint32_t& r2, uint32_t& r3,
                                              uint32_t addr) {
    asm volatile(
        "ldmatrix.sync.aligned.m8n8.x4.trans.shared.b16 {%0,%1,%2,%3}, [%4];"
        : "=r"(r0), "=r"(r1), "=r"(r2), "=r"(r3) : "r"(addr));
}
__device__ __forceinline__ void cp16(uint32_t dst, const void* src) {
    asm volatile("cp.async.cg.shared.global [%0], [%1], 16;"
                 :: "r"(dst), "l"(src));
}
#define CP_COMMIT() asm volatile("cp.async.commit_group;" ::: "memory")
template <int N>
__device__ __forceinline__ void cp_wait() {
    asm volatile("cp.async.wait_group %0;" :: "n"(N) : "memory");
}

// ---------------------------------------------------------------------------
// fp32 -> fp16 conversion prepass
// ---------------------------------------------------------------------------
__global__ void cvt_h(const float4* __restrict__ in, uint2* __restrict__ out,
                      int n4) {
    int i = blockIdx.x * blockDim.x + threadIdx.x;
    if (i >= n4) return;
    float4 v = in[i];
    out[i] = make_uint2(pack_h2(v.x, v.y), pack_h2(v.z, v.w));
}

// ---------------------------------------------------------------------------
// f16 GEMM: C[M,N] = alpha * A[M,K] @ B[N,K]^T, optional fused RoPE epilogue.
// A, B fp16 row-major. C half or float (template).
// BM=128, BN=64, BK=32, 256 threads (8 warps 4m x 2n), warp tile 32x32.
// Pitch 40 halves (fragment bank = 4g + c, conflict-free).
// ---------------------------------------------------------------------------
#define GAP 40

template <bool ROPE, bool CHALF>
__global__ __launch_bounds__(256) void gemm_h(const __half* __restrict__ A,
                                              const __half* __restrict__ B,
                                              void* __restrict__ Cp,
                                              int M, int N, int K,
                                              const float* __restrict__ cosb,
                                              const float* __restrict__ sinb,
                                              float alpha) {
    __shared__ __align__(16) __half As[128 * GAP];
    __shared__ __align__(16) __half Bs[64 * GAP];

    const int tid = threadIdx.x;
    const int wid = tid >> 5;
    const int lane = tid & 31;
    const int g = lane >> 2;
    const int c = lane & 3;
    const int wm = wid >> 1;
    const int wn = wid & 1;
    const int row0 = blockIdx.y * 128;
    const int col0 = blockIdx.x * 64;

    float acc[2][4][4] = {};

    for (int k0 = 0; k0 < K; k0 += 32) {
        // A: 128x32 halves = 2 uint4/thread. B: 64x32 = 1 uint4/thread.
#pragma unroll
        for (int i = 0; i < 2; i++) {
            int lin = tid + 256 * i;          // 0..511
            int r  = lin >> 2;                // 0..127
            int k8 = (lin & 3) << 3;          // 0,8,16,24
            *(uint4*)&As[r * GAP + k8] =
                *(const uint4*)&A[(size_t)(row0 + r) * K + k0 + k8];
        }
        {
            int r  = tid >> 2;                // 0..63
            int k8 = (tid & 3) << 3;
            *(uint4*)&Bs[r * GAP + k8] =
                *(const uint4*)&B[(size_t)(col0 + r) * K + k0 + k8];
        }
        __syncthreads();

#pragma unroll
        for (int kk = 0; kk < 2; kk++) {
            uint32_t a[2][4];
#pragma unroll
            for (int mt = 0; mt < 2; mt++) {
                int mb = wm * 32 + mt * 16;
                a[mt][0] = *(uint32_t*)&As[(mb + g)     * GAP + kk * 16 + 2 * c];
                a[mt][1] = *(uint32_t*)&As[(mb + g + 8) * GAP + kk * 16 + 2 * c];
                a[mt][2] = *(uint32_t*)&As[(mb + g)     * GAP + kk * 16 + 2 * c + 8];
                a[mt][3] = *(uint32_t*)&As[(mb + g + 8) * GAP + kk * 16 + 2 * c + 8];
            }
#pragma unroll
            for (int nt = 0; nt < 4; nt++) {
                int nb = wn * 32 + nt * 8;
                uint32_t b[2];
                b[0] = *(uint32_t*)&Bs[(nb + g) * GAP + kk * 16 + 2 * c];
                b[1] = *(uint32_t*)&Bs[(nb + g) * GAP + kk * 16 + 2 * c + 8];
#pragma unroll
                for (int mt = 0; mt < 2; mt++)
                    mma_f16(acc[mt][nt], a[mt], b);
            }
        }
        __syncthreads();
    }

    // Epilogue: optional scale + RoPE rotation, then store.
#pragma unroll
    for (int mt = 0; mt < 2; mt++) {
#pragma unroll
        for (int nt = 0; nt < 4; nt++) {
            int r = row0 + wm * 32 + mt * 16 + g;
            int col = col0 + wn * 32 + nt * 8 + 2 * c;
            float v0 = acc[mt][nt][0] * alpha;
            float v1 = acc[mt][nt][1] * alpha;
            float v2 = acc[mt][nt][2] * alpha;
            float v3 = acc[mt][nt][3] * alpha;
            if (ROPE) {
                int i = (col & 63) >> 1;
                float c0 = cosb[r * 32 + i],        s0 = sinb[r * 32 + i];
                float c1 = cosb[(r + 8) * 32 + i],  s1 = sinb[(r + 8) * 32 + i];
                float t0 = v0 * c0 - v1 * s0;
                float t1 = v0 * s0 + v1 * c0;
                float t2 = v2 * c1 - v3 * s1;
                float t3 = v2 * s1 + v3 * c1;
                v0 = t0; v1 = t1; v2 = t2; v3 = t3;
            }
            if (CHALF) {
                __half* C = (__half*)Cp;
                *(uint32_t*)&C[(size_t)r * N + col]       = pack_h2(v0, v1);
                *(uint32_t*)&C[(size_t)(r + 8) * N + col] = pack_h2(v2, v3);
            } else {
                float* C = (float*)Cp;
                *(float2*)&C[(size_t)r * N + col]       = make_float2(v0, v1);
                *(float2*)&C[(size_t)(r + 8) * N + col] = make_float2(v2, v3);
            }
        }
    }
}

// ---------------------------------------------------------------------------
// Flash attention, f16 m16n8k16, causal, GQA. fp16 in/out.
// 256 threads (8 warps); q-tile 128, k-tile 64. Warp w: rows [16w,16w+16).
// Q fragments hoisted to registers; P passes mma->mma in registers (the
// S C-fragment IS the PV A-fragment); K/V double-buffered via cp.async.
// Pitch 72 halves. Smem: Q 128x72 + 2x(K 64x72 + V 64x72) = 55296 B.
// ---------------------------------------------------------------------------
#define FP 72
#define FL_QS 0
#define FL_K0 (128 * FP)              // + buf*9216 halves
#define FL_V0 (FL_K0 + 64 * FP)
#define KVBUF (128 * FP)              // halves per (K,V) pair
#define FLASH_SMEM ((128 * FP + 2 * KVBUF) * 2)

extern __shared__ __half fsm[];

__global__ __launch_bounds__(256) void flash_f16(const __half* __restrict__ Q,
                                                 const __half* __restrict__ K,
                                                 const __half* __restrict__ V,
                                                 __half* __restrict__ O) {
    __half* Qs = fsm + FL_QS;

    const int qt = gridDim.x - 1 - blockIdx.x;   // big tiles first
    const int h  = blockIdx.y;
    const int kvh = h >> 2;
    const int tid = threadIdx.x;
    const int w = tid >> 5;
    const int lane = tid & 31;
    const int g = lane >> 2;
    const int c = lane & 3;
    const int q0 = qt * 128;
    const int qb = w * 16;

    const uint32_t sbase = smem_u32(fsm);
    const int lm_row = lane & 15;
    const int lm_cs  = (lane >> 4) & 1;

    const int NT = 2 * qt + 2;

    // cp.async loader for K/V tile kt into buffer buf.
    auto load_kv = [&](int kt, int buf) {
        const int k0 = kt * 64;
        uint32_t kb = sbase + (uint32_t)(FL_K0 + buf * KVBUF) * 2;
        uint32_t vb = sbase + (uint32_t)(FL_V0 + buf * KVBUF) * 2;
#pragma unroll
        for (int i = 0; i < 2; i++) {
            int lin = tid + 256 * i;    // 0..511
            int r  = lin >> 3;          // 0..63
            int d8 = (lin & 7) << 3;
            uint32_t off = (uint32_t)(r * FP + d8) * 2;
            cp16(kb + off, &K[(size_t)(k0 + r) * KVDIM + kvh * HD + d8]);
            cp16(vb + off, &V[(size_t)(k0 + r) * KVDIM + kvh * HD + d8]);
        }
        CP_COMMIT();
    };

    // Load Q tile to smem (plain stores) + kick off K/V tile 0.
#pragma unroll
    for (int i = 0; i < 4; i++) {
        int lin = tid + 256 * i;
        int r  = lin >> 3;
        int d8 = (lin & 7) << 3;
        *(uint4*)&Qs[r * FP + d8] =
            *(const uint4*)&Q[(size_t)(q0 + r) * DIM + h * HD + d8];
    }
    load_kv(0, 0);
    __syncthreads();   // Q stores visible

    // Hoist Q fragments into registers (invariant across k-tiles).
    uint32_t qf[4][4];
#pragma unroll
    for (int kk = 0; kk < 4; kk++) {
        qf[kk][0] = *(uint32_t*)&Qs[(qb + g)     * FP + kk * 16 + 2 * c];
        qf[kk][1] = *(uint32_t*)&Qs[(qb + g + 8) * FP + kk * 16 + 2 * c];
        qf[kk][2] = *(uint32_t*)&Qs[(qb + g)     * FP + kk * 16 + 2 * c + 8];
        qf[kk][3] = *(uint32_t*)&Qs[(qb + g + 8) * FP + kk * 16 + 2 * c + 8];
    }

    float m0 = -1e30f, m1 = -1e30f, l0 = 0.f, l1 = 0.f;
    float oacc[8][4] = {};

    for (int kt = 0; kt < NT; kt++) {
        const int buf = kt & 1;
        const int k0 = kt * 64;
        cp_wait<0>();
        __syncthreads();   // tile kt ready; prior compute done (buf reuse safe)

        if (kt + 1 < NT) load_kv(kt + 1, buf ^ 1);

        // Warp-uniform skip: tile entirely beyond this warp's last row.
        if (k0 > q0 + qb + 15) continue;

        __half* Ks = fsm + FL_K0 + buf * KVBUF;
        const uint32_t vbyte = sbase + (uint32_t)(FL_V0 + buf * KVBUF) * 2;

        // S = Q K^T : warp computes 16x64.
        float s[8][4] = {};
#pragma unroll
        for (int kk = 0; kk < 4; kk++) {
#pragma unroll
            for (int nt = 0; nt < 8; nt++) {
                uint32_t b[2];
                b[0] = *(uint32_t*)&Ks[(nt * 8 + g) * FP + kk * 16 + 2 * c];
                b[1] = *(uint32_t*)&Ks[(nt * 8 + g) * FP + kk * 16 + 2 * c + 8];
                mma_f16(s[nt], qf[kk], b);
            }
        }

        // Causal mask (only tiles crossing the diagonal).
        if (kt >= 2 * qt) {
            int r0 = q0 + qb + g, r1 = r0 + 8;
#pragma unroll
            for (int nt = 0; nt < 8; nt++) {
                int col = k0 + nt * 8 + 2 * c;
                if (col     > r0) s[nt][0] = -1e30f;
                if (col + 1 > r0) s[nt][1] = -1e30f;
                if (col     > r1) s[nt][2] = -1e30f;
                if (col + 1 > r1) s[nt][3] = -1e30f;
            }
        }

        // Online softmax.
        float mx0 = -1e30f, mx1 = -1e30f;
#pragma unroll
        for (int nt = 0; nt < 8; nt++) {
            mx0 = fmaxf(mx0, fmaxf(s[nt][0], s[nt][1]));
            mx1 = fmaxf(mx1, fmaxf(s[nt][2], s[nt][3]));
        }
        mx0 = fmaxf(mx0, __shfl_xor_sync(0xffffffffu, mx0, 1));
        mx0 = fmaxf(mx0, __shfl_xor_sync(0xffffffffu, mx0, 2));
        mx1 = fmaxf(mx1, __shfl_xor_sync(0xffffffffu, mx1, 1));
        mx1 = fmaxf(mx1, __shfl_xor_sync(0xffffffffu, mx1, 2));

        float mn0 = fmaxf(m0, mx0), mn1 = fmaxf(m1, mx1);
        float al0 = __expf(m0 - mn0), al1 = __expf(m1 - mn1);
        float sum0 = 0.f, sum1 = 0.f;
#pragma unroll
        for (int nt = 0; nt < 8; nt++) {
            s[nt][0] = __expf(s[nt][0] - mn0);
            s[nt][1] = __expf(s[nt][1] - mn0);
            s[nt][2] = __expf(s[nt][2] - mn1);
            s[nt][3] = __expf(s[nt][3] - mn1);
            sum0 += s[nt][0] + s[nt][1];
            sum1 += s[nt][2] + s[nt][3];
        }
        sum0 += __shfl_xor_sync(0xffffffffu, sum0, 1);
        sum0 += __shfl_xor_sync(0xffffffffu, sum0, 2);
        sum1 += __shfl_xor_sync(0xffffffffu, sum1, 1);
        sum1 += __shfl_xor_sync(0xffffffffu, sum1, 2);
        l0 = l0 * al0 + sum0;  m0 = mn0;
        l1 = l1 * al1 + sum1;  m1 = mn1;
#pragma unroll
        for (int nt = 0; nt < 8; nt++) {
            oacc[nt][0] *= al0; oacc[nt][1] *= al0;
            oacc[nt][2] *= al1; oacc[nt][3] *= al1;
        }

        // O += P V. P A-fragments come straight from S C-fragments:
        //   a[0]=pack(s[2kk][0],s[2kk][1])  (row g,   keys 16kk+2c,+1)
        //   a[1]=pack(s[2kk][2],s[2kk][3])  (row g+8, ...)
        //   a[2]=pack(s[2kk+1][0],[1])      (row g,   keys 16kk+8+2c)
        //   a[3]=pack(s[2kk+1][2],[3])
#pragma unroll
        for (int kk = 0; kk < 4; kk++) {
            uint32_t a[4];
            a[0] = pack_h2(s[2 * kk][0],     s[2 * kk][1]);
            a[1] = pack_h2(s[2 * kk][2],     s[2 * kk][3]);
            a[2] = pack_h2(s[2 * kk + 1][0], s[2 * kk + 1][1]);
            a[3] = pack_h2(s[2 * kk + 1][2], s[2 * kk + 1][3]);
#pragma unroll
            for (int ntp = 0; ntp < 4; ntp++) {
                uint32_t addr = vbyte +
                    (uint32_t)(kk * 16 + lm_row) * (FP * 2) +
                    (uint32_t)(16 * ntp + 8 * lm_cs) * 2;
                uint32_t b0, b1, b2, b3;
                ldsm_x4_trans(b0, b1, b2, b3, addr);
                uint32_t blo[2] = {b0, b1}, bhi[2] = {b2, b3};
                mma_f16(oacc[2 * ntp],     a, blo);
                mma_f16(oacc[2 * ntp + 1], a, bhi);
            }
        }
    }

    // Normalize and write fp16 output.
    float inv0 = 1.f / l0, inv1 = 1.f / l1;
    int r0 = q0 + qb + g;
#pragma unroll
    for (int nt = 0; nt < 8; nt++) {
        int col = h * HD + nt * 8 + 2 * c;
        *(uint32_t*)&O[(size_t)r0 * DIM + col] =
            pack_h2(oacc[nt][0] * inv0, oacc[nt][1] * inv0);
        *(uint32_t*)&O[(size_t)(r0 + 8) * DIM + col] =
            pack_h2(oacc[nt][2] * inv1, oacc[nt][3] * inv1);
    }
}

// ---------------------------------------------------------------------------
// Launch
// ---------------------------------------------------------------------------
extern "C" void kernel_launch(void* const* d_in, const int* in_sizes, int n_in,
                              void* d_out, int out_size) {
    const float* x  = (const float*)d_in[0];
    const float* fc = (const float*)d_in[1];
    const float* fs = (const float*)d_in[2];
    const float* wq = (const float*)d_in[3];
    const float* wk = (const float*)d_in[4];
    const float* wv = (const float*)d_in[5];
    const float* wo = (const float*)d_in[6];
    float* out = (float*)d_out;

    static __half *pq = nullptr, *pk, *pv, *pa, *px, *pwq, *pwk, *pwv, *pwo;
    if (!pq) {
        cudaGetSymbolAddress((void**)&pq,  g_qh);
        cudaGetSymbolAddress((void**)&pk,  g_kh);
        cudaGetSymbolAddress((void**)&pv,  g_vh);
        cudaGetSymbolAddress((void**)&pa,  g_ah);
        cudaGetSymbolAddress((void**)&px,  g_xh);
        cudaGetSymbolAddress((void**)&pwq, g_wqh);
        cudaGetSymbolAddress((void**)&pwk, g_wkh);
        cudaGetSymbolAddress((void**)&pwv, g_wvh);
        cudaGetSymbolAddress((void**)&pwo, g_woh);
        cudaFuncSetAttribute(flash_f16,
                             cudaFuncAttributeMaxDynamicSharedMemorySize,
                             FLASH_SMEM);
    }

    // fp32 -> fp16 prepass (x + all weights).
    auto cvt = [&](const float* src, __half* dst, int n) {
        cvt_h<<<(n / 4 + 255) / 256, 256>>>((const float4*)src, (uint2*)dst,
                                            n / 4);
    };
    cvt(x,  px,  SEQ * DIM);
    cvt(wq, pwq, DIM * DIM);
    cvt(wk, pwk, KVDIM * DIM);
    cvt(wv, pwv, KVDIM * DIM);
    cvt(wo, pwo, DIM * DIM);

    dim3 blk(256);
    // Q proj: rope + 1/sqrt(64) scale fused, half out.
    gemm_h<true, true><<<dim3(DIM / 64, SEQ / 128), blk>>>(
        px, pwq, pq, SEQ, DIM, DIM, fc, fs, 0.125f);
    // K proj: rope fused, half out.
    gemm_h<true, true><<<dim3(KVDIM / 64, SEQ / 128), blk>>>(
        px, pwk, pk, SEQ, KVDIM, DIM, fc, fs, 1.0f);
    // V proj: half out.
    gemm_h<false, true><<<dim3(KVDIM / 64, SEQ / 128), blk>>>(
        px, pwv, pv, SEQ, KVDIM, DIM, nullptr, nullptr, 1.0f);

    // Flash attention.
    flash_f16<<<dim3(SEQ / 128, NHEADS), blk, FLASH_SMEM>>>(pq, pk, pv, pa);

    // O proj: half operands, float out.
    gemm_h<false, false><<<dim3(DIM / 64, SEQ / 128), blk>>>(
        pa, pwo, out, SEQ, DIM, DIM, nullptr, nullptr, 1.0f);
}